// round 17
// baseline (speedup 1.0000x reference)
#include <cuda_runtime.h>
#include <cstddef>
#include <cstdint>

#define NN 100000
#define NE 1600000
#define DIM 64
#define N_LAYERS 6
#define UNIT 16              // nodes per work unit (per warp)
#define NUNITS (NN / UNIT)   // 6250
#define NWARPS 18
#define NTHREADS (NWARPS * 32)   // 576
#define ROUND 8              // edges per cp.async round
#define DEPTH 3              // pipeline depth (slots per warp)
#define SLOTF (ROUND * 64)   // floats per slot = 512 (2 KB)

// ---------------- scratch (no allocations allowed) ----------------
__device__ float g_h1[NN * DIM];
__device__ float g_h2[NN * DIM];
__device__ int   g_deg[NN];
__device__ int   g_off[NN + 1];
__device__ int   g_cur[NN];
__device__ int   g_csrc[NE];
__device__ int   g_tk[8];        // per-layer ticket counters

typedef unsigned long long u64;

__device__ __forceinline__ u64 pk2(float x, float y) {
    u64 r; asm("mov.b64 %0,{%1,%2};" : "=l"(r) : "f"(x), "f"(y)); return r;
}
__device__ __forceinline__ void upk2(u64 v, float& x, float& y) {
    asm("mov.b64 {%0,%1},%2;" : "=f"(x), "=f"(y) : "l"(v));
}
__device__ __forceinline__ u64 f2fma(u64 a, u64 b, u64 c) {
    u64 d; asm("fma.rn.f32x2 %0,%1,%2,%3;" : "=l"(d) : "l"(a), "l"(b), "l"(c)); return d;
}
__device__ __forceinline__ u64 f2add(u64 a, u64 b) {
    u64 d; asm("add.rn.f32x2 %0,%1,%2;" : "=l"(d) : "l"(a), "l"(b)); return d;
}
__device__ __forceinline__ u64 relu2(u64 v) {
    float x, y; upk2(v, x, y);
    return pk2(fmaxf(x, 0.f), fmaxf(y, 0.f));
}
__device__ __forceinline__ float4 max4(float4 a, float4 b) {
    return make_float4(fmaxf(a.x, b.x), fmaxf(a.y, b.y),
                       fmaxf(a.z, b.z), fmaxf(a.w, b.w));
}
__device__ __forceinline__ uint32_t smem_u32(const void* p) {
    uint32_t a;
    asm("{ .reg .u64 t; cvta.to.shared.u64 t, %1; cvt.u32.u64 %0, t; }"
        : "=r"(a) : "l"(p));
    return a;
}

// ---------------- CSR build ----------------
__global__ void k_count(const int* __restrict__ ei) {
    int e = blockIdx.x * blockDim.x + threadIdx.x;
    if (e < NE) {
        int dst = ei[NE + e];
        if ((unsigned)dst < (unsigned)NN) atomicAdd(&g_deg[dst], 1);
    }
}

__global__ void k_scan() {
    __shared__ int sums[1024];
    int t = threadIdx.x;
    const int C = (NN + 1023) / 1024;
    int start = t * C;
    int end = start + C; if (end > NN) end = NN;
    if (start > NN) start = NN;
    int s = 0;
    for (int i = start; i < end; i++) s += g_deg[i];
    sums[t] = s;
    __syncthreads();
    for (int off = 1; off < 1024; off <<= 1) {
        int v = (t >= off) ? sums[t - off] : 0;
        __syncthreads();
        sums[t] += v;
        __syncthreads();
    }
    int base = (t == 0) ? 0 : sums[t - 1];
    for (int i = start; i < end; i++) {
        int d = g_deg[i];
        g_off[i] = base;
        g_cur[i] = base;
        base += d;
    }
    if (t == 1023) g_off[NN] = base;
    if (t < 8) g_tk[t] = 0;          // reset tickets every replay
}

__global__ void k_fill(const int* __restrict__ ei) {
    int e = blockIdx.x * blockDim.x + threadIdx.x;
    if (e < NE) {
        int src = ei[e];
        int dst = ei[NE + e];
        if ((unsigned)dst < (unsigned)NN && (unsigned)src < (unsigned)NN) {
            int p = atomicAdd(&g_cur[dst], 1);
            g_csrc[p] = src;
        }
    }
}

// ---------------- fused SAGE layer ----------------
// Gather: cp.async pipeline. Per warp, rounds of 8 edges copied gmem->smem
// (2 edges per warp cp.async instr, 16B/lane), DEPTH=3 rounds in flight.
// Readback: each lane LDS's exactly the bytes it copied (thread-scope
// visibility, no sync), max4 accumulate, shfl_xor(16) combine per node.
// agg rows stored in zbuf with XOR-chunk swizzle (conflict-free, no pad).
// Transform: thread = 4 nodes x 8 cols, 16 packed f32x2 accums (zero-init,
// bias at epilogue); k<64 z=agg (smem), k>=64 z=h (direct gmem broadcast).
__global__ __launch_bounds__(NTHREADS, 1) void k_sage(
    const float* __restrict__ hin_ext, float* __restrict__ hout_ext,
    int sel_in, int sel_out, int layer,
    const float* __restrict__ Wl, const float* __restrict__ bl,
    const float* __restrict__ Wr, int do_relu)
{
    extern __shared__ float sm[];
    float* wt   = sm;                         // 8192 f : [Wl;Wr]^T
    float* bias = sm + 8192;                  // 64 f
    float* zb   = sm + 8192 + 64;             // NWARPS*UNIT*64 agg rows (swizzled)
    float* stg  = zb + NWARPS * UNIT * 64;    // NWARPS*DEPTH*SLOTF staging

    const float* hin  = (sel_in  == 0) ? hin_ext  : (sel_in  == 1 ? g_h1 : g_h2);
    float*       hout = (sel_out == 0) ? hout_ext : (sel_out == 1 ? g_h1 : g_h2);

    int tid = threadIdx.x;
    for (int i = tid; i < 64 * 64; i += NTHREADS) {
        int j = i >> 6, k = i & 63;
        wt[k * 64 + j]        = Wl[i];
        wt[(64 + k) * 64 + j] = Wr[i];
    }
    if (tid < 64) bias[tid] = bl[tid];
    __syncthreads();

    int w = tid >> 5, lane = tid & 31;
    int half = lane >> 4, c16 = lane & 15;        // gather mapping
    int nidx = lane >> 3, jidx = lane & 7;        // transform mapping
    float* zw = zb + w * (UNIT * 64);
    float* sw = stg + w * (DEPTH * SLOTF);
    uint32_t sw_base = smem_u32(sw) + (uint32_t)(half * 64 * 4 + c16 * 16);

    while (true) {
        int u;
        if (lane == 0) u = atomicAdd(&g_tk[layer], 1);
        u = __shfl_sync(0xffffffffu, u, 0);
        if (u >= NUNITS) break;
        int nb = u * UNIT;

        // ================= gather: cp.async pipeline =================
        {
            int iln = 0, ir = 0, inflight = 0, islot = 0;
            int ibeg = g_off[nb], iend = g_off[nb + 1];
            int cln = 0, cr = 0, cslot = 0;
            int cbeg = ibeg, cend = iend;
            float4 m = make_float4(-3.4e38f, -3.4e38f, -3.4e38f, -3.4e38f);

            while (cln < UNIT) {
                // ---- issue phase: keep DEPTH rounds in flight ----
                while (inflight < DEPTH && iln < UNIT) {
                    int nr = (iend - ibeg + ROUND - 1) >> 3;
                    if (ir < nr) {
                        int base = ibeg + ir * ROUND;
                        uint32_t dst = sw_base + (uint32_t)(islot * SLOTF * 4);
                        #pragma unroll
                        for (int e2 = 0; e2 < 4; e2++) {
                            int e = base + e2 * 2 + half;
                            e = (e < iend) ? e : (iend - 1);
                            int s = g_csrc[e];
                            const float* srcp = hin + (size_t)s * DIM + c16 * 4;
                            asm volatile(
                                "cp.async.ca.shared.global [%0], [%1], 16;"
                                :: "r"(dst + (uint32_t)(e2 * 2 * 64 * 4)), "l"(srcp)
                                : "memory");
                        }
                        asm volatile("cp.async.commit_group;" ::: "memory");
                        inflight++;
                        islot = (islot + 1 == DEPTH) ? 0 : islot + 1;
                        ir++;
                        if (ir >= nr) {
                            iln++; ir = 0;
                            if (iln < UNIT) { ibeg = iend; iend = g_off[nb + iln + 1]; }
                        }
                    } else {                 // zero-edge node: no rounds
                        iln++;
                        if (iln < UNIT) { ibeg = iend; iend = g_off[nb + iln + 1]; }
                    }
                }
                // ---- consume phase: one round (or finalize node) ----
                int cnr = (cend - cbeg + ROUND - 1) >> 3;
                if (cr < cnr) {
                    if (inflight >= 3)      asm volatile("cp.async.wait_group 2;" ::: "memory");
                    else if (inflight == 2) asm volatile("cp.async.wait_group 1;" ::: "memory");
                    else                    asm volatile("cp.async.wait_group 0;" ::: "memory");
                    const float* cp = sw + cslot * SLOTF + half * 64 + c16 * 4;
                    #pragma unroll
                    for (int e2 = 0; e2 < 4; e2++) {
                        float4 v = *(const float4*)(cp + e2 * 2 * 64);
                        m = max4(m, v);
                    }
                    cr++; inflight--;
                    cslot = (cslot + 1 == DEPTH) ? 0 : cslot + 1;
                }
                if (cr >= cnr) {
                    // finalize node cln
                    m.x = fmaxf(m.x, __shfl_xor_sync(0xffffffffu, m.x, 16));
                    m.y = fmaxf(m.y, __shfl_xor_sync(0xffffffffu, m.y, 16));
                    m.z = fmaxf(m.z, __shfl_xor_sync(0xffffffffu, m.z, 16));
                    m.w = fmaxf(m.w, __shfl_xor_sync(0xffffffffu, m.w, 16));
                    if (cbeg == cend) m = make_float4(0.f, 0.f, 0.f, 0.f);
                    if (half == 0) {
                        int swz = (cln >> 2) & 3;
                        *(float4*)&zw[cln * 64 + ((c16 ^ swz) << 2)] = m;
                    }
                    m = make_float4(-3.4e38f, -3.4e38f, -3.4e38f, -3.4e38f);
                    cln++; cr = 0;
                    if (cln < UNIT) { cbeg = cend; cend = g_off[nb + cln + 1]; }
                }
            }
        }
        __syncwarp();

        // ================= transform =================
        {
            int n0 = nb + 4 * nidx;
            const float* zr = zw + 4 * nidx * 64;            // 4 agg rows (swz = nidx)
            const float* rh = hin + (size_t)n0 * DIM;        // 4 h rows

            u64 a0[4], a1[4], a2[4], a3[4];
            #pragma unroll
            for (int i = 0; i < 4; i++) { a0[i] = 0ull; a1[i] = 0ull; a2[i] = 0ull; a3[i] = 0ull; }

            // half 1: k in [0,64) -> z = agg from swizzled smem
            #pragma unroll 2
            for (int k4 = 0; k4 < 64; k4 += 4) {
                int off = ((k4 >> 2) ^ nidx) << 2;
                float4 zv[4];
                #pragma unroll
                for (int i = 0; i < 4; i++)
                    zv[i] = *(const float4*)&zr[i * 64 + off];
                #pragma unroll
                for (int kk = 0; kk < 4; kk++) {
                    int k = k4 + kk;
                    ulonglong2 wa = *(const ulonglong2*)&wt[k * 64 + jidx * 8];
                    ulonglong2 wb = *(const ulonglong2*)&wt[k * 64 + jidx * 8 + 4];
                    #pragma unroll
                    for (int i = 0; i < 4; i++) {
                        float f = (kk == 0) ? zv[i].x : (kk == 1) ? zv[i].y
                                : (kk == 2) ? zv[i].z : zv[i].w;
                        u64 p = pk2(f, f);
                        a0[i] = f2fma(p, wa.x, a0[i]);
                        a1[i] = f2fma(p, wa.y, a1[i]);
                        a2[i] = f2fma(p, wb.x, a2[i]);
                        a3[i] = f2fma(p, wb.y, a3[i]);
                    }
                }
            }
            // half 2: k in [64,128) -> z = h direct from gmem (broadcast lanes)
            #pragma unroll 2
            for (int k4 = 0; k4 < 64; k4 += 4) {
                float4 zv[4];
                #pragma unroll
                for (int i = 0; i < 4; i++)
                    zv[i] = *(const float4*)(rh + i * DIM + k4);
                #pragma unroll
                for (int kk = 0; kk < 4; kk++) {
                    int k = 64 + k4 + kk;
                    ulonglong2 wa = *(const ulonglong2*)&wt[k * 64 + jidx * 8];
                    ulonglong2 wb = *(const ulonglong2*)&wt[k * 64 + jidx * 8 + 4];
                    #pragma unroll
                    for (int i = 0; i < 4; i++) {
                        float f = (kk == 0) ? zv[i].x : (kk == 1) ? zv[i].y
                                : (kk == 2) ? zv[i].z : zv[i].w;
                        u64 p = pk2(f, f);
                        a0[i] = f2fma(p, wa.x, a0[i]);
                        a1[i] = f2fma(p, wa.y, a1[i]);
                        a2[i] = f2fma(p, wb.x, a2[i]);
                        a3[i] = f2fma(p, wb.y, a3[i]);
                    }
                }
            }
            // epilogue: + bias, relu, store
            u64 pb0 = *(const u64*)&bias[jidx * 8 + 0];
            u64 pb1 = *(const u64*)&bias[jidx * 8 + 2];
            u64 pb2 = *(const u64*)&bias[jidx * 8 + 4];
            u64 pb3 = *(const u64*)&bias[jidx * 8 + 6];
            #pragma unroll
            for (int i = 0; i < 4; i++) {
                u64 v0 = f2add(a0[i], pb0), v1 = f2add(a1[i], pb1);
                u64 v2 = f2add(a2[i], pb2), v3 = f2add(a3[i], pb3);
                if (do_relu) { v0 = relu2(v0); v1 = relu2(v1); v2 = relu2(v2); v3 = relu2(v3); }
                int node = n0 + i;
                ulonglong2 s0, s1;
                s0.x = v0; s0.y = v1; s1.x = v2; s1.y = v3;
                *(ulonglong2*)(hout + (size_t)node * DIM + jidx * 8)     = s0;
                *(ulonglong2*)(hout + (size_t)node * DIM + jidx * 8 + 4) = s1;
            }
        }
        __syncwarp();
    }
}

// ---------------- launch ----------------
extern "C" void kernel_launch(void* const* d_in, const int* in_sizes, int n_in,
                              void* d_out, int out_size)
{
    const float* x  = (const float*)d_in[0];
    const int*   ei = (const int*)d_in[1];
    const float* Wl = (const float*)d_in[2];
    const float* bl = (const float*)d_in[3];
    const float* Wr = (const float*)d_in[4];
    float*       out = (float*)d_out;

    const int SMEM = (8192 + 64 + NWARPS * UNIT * 64 + NWARPS * DEPTH * SLOTF) * 4;
    // = (8192+64+18432+27648)*4 = 217,344 B
    cudaFuncSetAttribute(k_sage, cudaFuncAttributeMaxDynamicSharedMemorySize, SMEM);

    void* deg_ptr = nullptr;
    cudaGetSymbolAddress(&deg_ptr, g_deg);
    cudaMemsetAsync(deg_ptr, 0, NN * sizeof(int));

    k_count<<<(NE + 255) / 256, 256>>>(ei);
    k_scan<<<1, 1024>>>();
    k_fill<<<(NE + 255) / 256, 256>>>(ei);

    const int GRID = 148;  // 1 persistent block per SM
    // ping-pong: ext(x) -> g_h1 -> g_h2 -> g_h1 -> g_h2 -> g_h1 -> ext(out)
    int sel_in = 0, sel_out = 1;
    for (int l = 0; l < N_LAYERS; l++) {
        int so = (l == N_LAYERS - 1) ? 0 : sel_out;
        k_sage<<<GRID, NTHREADS, SMEM>>>(x, out, sel_in, so, l,
                                         Wl + (size_t)l * DIM * DIM,
                                         bl + (size_t)l * DIM,
                                         Wr + (size_t)l * DIM * DIM,
                                         (l < N_LAYERS - 1) ? 1 : 0);
        if (l < N_LAYERS - 1) {
            sel_in = sel_out;
            sel_out = (sel_out == 1) ? 2 : 1;
        }
    }
}